// round 14
// baseline (speedup 1.0000x reference)
#include <cuda_runtime.h>
#include <cuda_bf16.h>
#include <cuda_fp16.h>
#include <cstdint>

typedef unsigned long long ull;
typedef unsigned int u32;
typedef __nv_bfloat16 bf16;

// ---------- cp.async ----------
__device__ __forceinline__ void cpa16(u32 d, const void* s) {
    asm volatile("cp.async.cg.shared.global [%0], [%1], 16;" :: "r"(d), "l"(s));
}
#define CP_COMMIT() asm volatile("cp.async.commit_group;")
// ---------- mma.sync / ldmatrix ----------
__device__ __forceinline__ u32 s2u(const void* p) { return (u32)__cvta_generic_to_shared(p); }
__device__ __forceinline__ void ldsm4(u32* r, u32 a) {
    asm volatile("ldmatrix.sync.aligned.m8n8.x4.shared.b16 {%0,%1,%2,%3}, [%4];"
                 : "=r"(r[0]), "=r"(r[1]), "=r"(r[2]), "=r"(r[3]) : "r"(a));
}
__device__ __forceinline__ void mma16816(float* c, const u32* a, u32 b0, u32 b1) {
    asm volatile("mma.sync.aligned.m16n8k16.row.col.f32.bf16.bf16.f32 "
                 "{%0,%1,%2,%3}, {%4,%5,%6,%7}, {%8,%9}, {%0,%1,%2,%3};"
                 : "+f"(c[0]), "+f"(c[1]), "+f"(c[2]), "+f"(c[3])
                 : "r"(a[0]), "r"(a[1]), "r"(a[2]), "r"(a[3]), "r"(b0), "r"(b1));
}
__device__ __forceinline__ void mma16816h(float* c, const u32* a, u32 b0, u32 b1) {
    asm volatile("mma.sync.aligned.m16n8k16.row.col.f32.f16.f16.f32 "
                 "{%0,%1,%2,%3}, {%4,%5,%6,%7}, {%8,%9}, {%0,%1,%2,%3};"
                 : "+f"(c[0]), "+f"(c[1]), "+f"(c[2]), "+f"(c[3])
                 : "r"(a[0]), "r"(a[1]), "r"(a[2]), "r"(a[3]), "r"(b0), "r"(b1));
}
__device__ __forceinline__ u32 pk2(float up, float lo) {
    u32 d; asm("cvt.rn.bf16x2.f32 %0, %1, %2;" : "=r"(d) : "f"(up), "f"(lo)); return d;
}

#define KP 320
__device__ bf16 g_Ahi[16L * 2048 * KP], g_Alo[16L * 2048 * KP];
__device__ bf16 g_I2hi[16L * 512 * KP], g_I2lo[16L * 512 * KP];
__device__ bf16 g_Wsphi[2L * 384 * KP], g_Wsplo[2L * 384 * KP];       // pads zero-init
__device__ bf16 g_Whi[2L * 16 * 512 * KP], g_Wlo[2L * 16 * 512 * KP]; // cols>=300 zero-init
__device__ __half g_V16[16L * 320 * 512];                              // rows 300..319 zero-init
__device__ __half g_P16[2L * 16 * 2048 * 512];

// stage rows x 64-col 16-bit tile (128B rows), XOR swizzle; 256 threads
__device__ __forceinline__ void ldt(u32 dst, const bf16* src, int pitch, int k0, int rows) {
    for (int i = threadIdx.x; i < rows * 8; i += 256) {
        int r = i >> 3, c = i & 7;
        cpa16(dst + r * 128 + ((c ^ (r & 7)) << 4), src + (size_t)r * pitch + k0 + c * 8);
    }
}

__global__ void split_in1(const float* __restrict__ in1) {
    size_t i = (size_t)blockIdx.x * 256 + threadIdx.x;
    if (i >= 16L * 2048 * KP) return;
    int k = (int)(i % KP); size_t bt = i / KP;
    float v = (k < 300) ? in1[bt * 300 + k] : 0.f;
    bf16 h = __float2bfloat16(v);
    g_Ahi[i] = h; g_Alo[i] = __float2bfloat16(v - __bfloat162float(h));
}

__global__ void split_in2(const float* __restrict__ in2) {
    size_t i = (size_t)blockIdx.x * 256 + threadIdx.x;
    if (i >= 16L * 512 * KP) return;
    int k = (int)(i % KP); size_t bw = i / KP;
    float v = (k < 300) ? in2[bw * 300 + k] : 0.f;
    bf16 h = __float2bfloat16(v);
    g_I2hi[i] = h; g_I2lo[i] = __float2bfloat16(v - __bfloat162float(h));
}

__global__ void wsplit_kernel(const float* __restrict__ W2, const float* __restrict__ W3) {
    int idx = blockIdx.x * blockDim.x + threadIdx.x;
    if (idx >= 2 * 300 * 300) return;
    int h = idx / (300 * 300), rem = idx - h * (300 * 300);
    int e = rem / 300, d = rem - e * 300;
    float v = (h ? W3 : W2)[e * 300 + d];
    bf16 hi = __float2bfloat16(v);
    size_t o = ((size_t)h * 384 + e) * KP + d;
    g_Wsphi[o] = hi; g_Wsplo[o] = __float2bfloat16(v - __bfloat162float(hi));
}

// V16[b][d][w] = fp16(in2[b][w][d])
__global__ void vt_kernel(const float* __restrict__ in2) {
    __shared__ float t[32][33];
    const int b = blockIdx.z, d0 = blockIdx.y * 32, w0 = blockIdx.x * 32;
    const int tx = threadIdx.x, ty = threadIdx.y;
    for (int yy = ty; yy < 32; yy += 8)
        t[yy][tx] = (d0 + tx < 300) ? in2[((size_t)b * 512 + w0 + yy) * 300 + d0 + tx] : 0.f;
    __syncthreads();
    for (int yy = ty; yy < 32; yy += 8)
        g_V16[((size_t)b * 320 + d0 + yy) * 512 + w0 + tx] = __float2half(t[tx][yy]);
}

// ========== 3-product bf16 GEMM core, 2-stage ==========
template<int NCHUNK, int GN>
__device__ __forceinline__ void gemm3(u32 sb, const bf16* Ah, const bf16* Al,
                                      const bf16* Bh, const bf16* Bl,
                                      int pitch, float acc[4][2 * GN][4]) {
    constexpr int BN = 64 * GN;
    constexpr u32 ASZ = 128 * 128;
    constexpr u32 BSZ = (u32)BN * 128;
    constexpr u32 STAGE = 2 * ASZ + 2 * BSZ;
    const int lane = threadIdx.x & 31, wid = threadIdx.x >> 5;
    const int wm = wid >> 2, wn = wid & 3;
    ldt(sb, Ah, pitch, 0, 128);             ldt(sb + ASZ, Al, pitch, 0, 128);
    ldt(sb + 2 * ASZ, Bh, pitch, 0, BN);    ldt(sb + 2 * ASZ + BSZ, Bl, pitch, 0, BN);
    CP_COMMIT();
    const int rA = wm * 64 + (lane & 15), rB = wn * (GN * 16) + (lane & 15);
    const int chalf = lane >> 4;
    for (int kc = 0; kc < NCHUNK; ++kc) {
        if (kc + 1 < NCHUNK) {
            u32 d = sb + ((kc + 1) & 1) * STAGE;
            int k0 = (kc + 1) * 64;
            ldt(d, Ah, pitch, k0, 128);          ldt(d + ASZ, Al, pitch, k0, 128);
            ldt(d + 2 * ASZ, Bh, pitch, k0, BN); ldt(d + 2 * ASZ + BSZ, Bl, pitch, k0, BN);
            CP_COMMIT();
            asm volatile("cp.async.wait_group 1;");
        } else {
            asm volatile("cp.async.wait_group 0;");
        }
        __syncthreads();
        u32 st = sb + (kc & 1) * STAGE;
#pragma unroll
        for (int ks = 0; ks < 4; ++ks) {
            const int c16 = ks * 2 + chalf;
            const u32 offA = rA * 128 + (((u32)(c16 ^ (rA & 7))) << 4);
            const u32 offB = rB * 128 + (((u32)(c16 ^ (rB & 7))) << 4);
            u32 ah[4][4], al[4][4], bh[GN][4], bl[GN][4];
#pragma unroll
            for (int mi = 0; mi < 4; ++mi) {
                ldsm4(ah[mi], st + offA + mi * 2048);
                ldsm4(al[mi], st + ASZ + offA + mi * 2048);
            }
#pragma unroll
            for (int g = 0; g < GN; ++g) {
                ldsm4(bh[g], st + 2 * ASZ + offB + g * 2048);
                ldsm4(bl[g], st + 2 * ASZ + BSZ + offB + g * 2048);
            }
#pragma unroll
            for (int mi = 0; mi < 4; ++mi)
#pragma unroll
                for (int g = 0; g < GN; ++g)
#pragma unroll
                    for (int sub = 0; sub < 2; ++sub) {
                        float* c = acc[mi][g * 2 + sub];
                        mma16816(c, ah[mi], bh[g][sub], bh[g][sub + 2]);
                        mma16816(c, ah[mi], bl[g][sub], bl[g][sub + 2]);
                        mma16816(c, al[mi], bh[g][sub], bh[g][sub + 2]);
                    }
        }
        __syncthreads();
    }
}

// ========== 3-product bf16 GEMM core, SINGLE stage (for fused half1) ==========
template<int NCHUNK, int GN>
__device__ __forceinline__ void gemm3_1s(u32 sb, const bf16* Ah, const bf16* Al,
                                         const bf16* Bh, const bf16* Bl,
                                         int pitch, float acc[4][2 * GN][4]) {
    constexpr int BN = 64 * GN;
    constexpr u32 ASZ = 128 * 128;
    constexpr u32 BSZ = (u32)BN * 128;
    const int lane = threadIdx.x & 31, wid = threadIdx.x >> 5;
    const int wm = wid >> 2, wn = wid & 3;
    const int rA = wm * 64 + (lane & 15), rB = wn * (GN * 16) + (lane & 15);
    const int chalf = lane >> 4;
    for (int kc = 0; kc < NCHUNK; ++kc) {
        int k0 = kc * 64;
        ldt(sb, Ah, pitch, k0, 128);          ldt(sb + ASZ, Al, pitch, k0, 128);
        ldt(sb + 2 * ASZ, Bh, pitch, k0, BN); ldt(sb + 2 * ASZ + BSZ, Bl, pitch, k0, BN);
        CP_COMMIT();
        asm volatile("cp.async.wait_group 0;");
        __syncthreads();
#pragma unroll
        for (int ks = 0; ks < 4; ++ks) {
            const int c16 = ks * 2 + chalf;
            const u32 offA = rA * 128 + (((u32)(c16 ^ (rA & 7))) << 4);
            const u32 offB = rB * 128 + (((u32)(c16 ^ (rB & 7))) << 4);
            u32 ah[4][4], al[4][4], bh[GN][4], bl[GN][4];
#pragma unroll
            for (int mi = 0; mi < 4; ++mi) {
                ldsm4(ah[mi], sb + offA + mi * 2048);
                ldsm4(al[mi], sb + ASZ + offA + mi * 2048);
            }
#pragma unroll
            for (int g = 0; g < GN; ++g) {
                ldsm4(bh[g], sb + 2 * ASZ + offB + g * 2048);
                ldsm4(bl[g], sb + 2 * ASZ + BSZ + offB + g * 2048);
            }
#pragma unroll
            for (int mi = 0; mi < 4; ++mi)
#pragma unroll
                for (int g = 0; g < GN; ++g)
#pragma unroll
                    for (int sub = 0; sub < 2; ++sub) {
                        float* c = acc[mi][g * 2 + sub];
                        mma16816(c, ah[mi], bh[g][sub], bh[g][sub + 2]);
                        mma16816(c, ah[mi], bl[g][sub], bl[g][sub + 2]);
                        mma16816(c, al[mi], bh[g][sub], bh[g][sub + 2]);
                    }
        }
        __syncthreads();
    }
}

// ========== single-product fp16 GEMM core (out), 2-stage ==========
template<int NCHUNK, int GN>
__device__ __forceinline__ void gemm1(u32 sb, const bf16* A, const bf16* B,
                                      int pitch, float acc[4][2 * GN][4]) {
    constexpr int BN = 64 * GN;
    constexpr u32 ASZ = 128 * 128;
    constexpr u32 BSZ = (u32)BN * 128;
    constexpr u32 STAGE = ASZ + BSZ;
    const int lane = threadIdx.x & 31, wid = threadIdx.x >> 5;
    const int wm = wid >> 2, wn = wid & 3;
    ldt(sb, A, pitch, 0, 128);
    ldt(sb + ASZ, B, pitch, 0, BN);
    CP_COMMIT();
    const int rA = wm * 64 + (lane & 15), rB = wn * (GN * 16) + (lane & 15);
    const int chalf = lane >> 4;
    for (int kc = 0; kc < NCHUNK; ++kc) {
        if (kc + 1 < NCHUNK) {
            u32 d = sb + ((kc + 1) & 1) * STAGE;
            int k0 = (kc + 1) * 64;
            ldt(d, A, pitch, k0, 128);
            ldt(d + ASZ, B, pitch, k0, BN);
            CP_COMMIT();
            asm volatile("cp.async.wait_group 1;");
        } else {
            asm volatile("cp.async.wait_group 0;");
        }
        __syncthreads();
        u32 st = sb + (kc & 1) * STAGE;
#pragma unroll
        for (int ks = 0; ks < 4; ++ks) {
            const int c16 = ks * 2 + chalf;
            const u32 offA = rA * 128 + (((u32)(c16 ^ (rA & 7))) << 4);
            const u32 offB = rB * 128 + (((u32)(c16 ^ (rB & 7))) << 4);
            u32 ah[4][4], bh[GN][4];
#pragma unroll
            for (int mi = 0; mi < 4; ++mi) ldsm4(ah[mi], st + offA + mi * 2048);
#pragma unroll
            for (int g = 0; g < GN; ++g)  ldsm4(bh[g], st + ASZ + offB + g * 2048);
#pragma unroll
            for (int mi = 0; mi < 4; ++mi)
#pragma unroll
                for (int g = 0; g < GN; ++g)
#pragma unroll
                    for (int sub = 0; sub < 2; ++sub)
                        mma16816h(acc[mi][g * 2 + sub], ah[mi], bh[g][sub], bh[g][sub + 2]);
        }
        __syncthreads();
    }
}

#define SMEM_GN2 131072
#define SMEM_OUT 172032
#define SMEM_SS  231424
// fused kernel smem layout
#define P0_OFF   98304
#define P1_OFF   163840
#define RED_OFF  163840
#define MA0_OFF  229376
#define SA0_OFF  229888
#define MA1_OFF  230400
#define SA1_OFF  230912

#define ACC_ZERO(acc, GN) do { _Pragma("unroll") for (int _i = 0; _i < 4; ++_i) \
    _Pragma("unroll") for (int _j = 0; _j < 2 * (GN); ++_j) \
    _Pragma("unroll") for (int _q = 0; _q < 4; ++_q) acc[_i][_j][_q] = 0.f; } while (0)

// per-half row softmax stats: m/sum per row; acc replaced by exp(acc - m[row])
__device__ __forceinline__ void rowsoft(float acc[4][8][4], float* red,
                                        float* mArr, float* sArr) {
    const int tid = threadIdx.x, lane = tid & 31, wid = tid >> 5;
    const int wm = wid >> 2, wn = wid & 3;
    float lm[4][2];
#pragma unroll
    for (int mi = 0; mi < 4; ++mi)
#pragma unroll
        for (int h = 0; h < 2; ++h) {
            float v = -3.0e38f;
#pragma unroll
            for (int ni = 0; ni < 8; ++ni)
                v = fmaxf(v, fmaxf(acc[mi][ni][2 * h], acc[mi][ni][2 * h + 1]));
            v = fmaxf(v, __shfl_xor_sync(0xffffffffu, v, 1));
            v = fmaxf(v, __shfl_xor_sync(0xffffffffu, v, 2));
            lm[mi][h] = v;
        }
    if ((lane & 3) == 0)
#pragma unroll
        for (int mi = 0; mi < 4; ++mi)
#pragma unroll
            for (int h = 0; h < 2; ++h) {
                int r = wm * 64 + mi * 16 + (lane >> 2) + h * 8;
                red[r * 4 + wn] = lm[mi][h];
            }
    __syncthreads();
    if (tid < 128)
        mArr[tid] = fmaxf(fmaxf(red[tid * 4], red[tid * 4 + 1]),
                          fmaxf(red[tid * 4 + 2], red[tid * 4 + 3]));
    __syncthreads();
#pragma unroll
    for (int mi = 0; mi < 4; ++mi)
#pragma unroll
        for (int h = 0; h < 2; ++h) {
            int r = wm * 64 + mi * 16 + (lane >> 2) + h * 8;
            float m = mArr[r];
            float ps = 0.f;
#pragma unroll
            for (int ni = 0; ni < 8; ++ni) {
                float e0 = __expf(acc[mi][ni][2 * h] - m);
                float e1 = __expf(acc[mi][ni][2 * h + 1] - m);
                acc[mi][ni][2 * h] = e0; acc[mi][ni][2 * h + 1] = e1;
                ps += e0 + e1;
            }
            ps += __shfl_xor_sync(0xffffffffu, ps, 1);
            ps += __shfl_xor_sync(0xffffffffu, ps, 2);
            if ((lane & 3) == 0) red[r * 4 + wn] = ps;
        }
    __syncthreads();
    if (tid < 128)
        sArr[tid] = red[tid * 4] + red[tid * 4 + 1] + red[tid * 4 + 2] + red[tid * 4 + 3];
    __syncthreads();
}

// proj = in2 @ W^T + b -> g_Whi/g_Wlo ([h*8192 + b*512 + w][e])
__global__ __launch_bounds__(256) void proj_mma(const float* __restrict__ b2,
                                                const float* __restrict__ b3) {
    extern __shared__ char sm[];
    const u32 sb = s2u(sm);
    const int lane = threadIdx.x & 31, wid = threadIdx.x >> 5;
    const int wm = wid >> 2, wn = wid & 3;
    const int t0 = blockIdx.x * 128, n0 = blockIdx.y * 128, h = blockIdx.z;
    float acc[4][4][4]; ACC_ZERO(acc, 2);
    gemm3<5, 2>(sb, g_I2hi + (size_t)t0 * KP, g_I2lo + (size_t)t0 * KP,
                g_Wsphi + ((size_t)h * 384 + n0) * KP, g_Wsplo + ((size_t)h * 384 + n0) * KP,
                KP, acc);
    const float* bias = h ? b3 : b2;
    bf16* Whi = g_Whi + (size_t)h * 8192 * KP;
    bf16* Wlo = g_Wlo + (size_t)h * 8192 * KP;
#pragma unroll
    for (int mi = 0; mi < 4; ++mi)
#pragma unroll
        for (int ni = 0; ni < 4; ++ni) {
            int row = t0 + wm * 64 + mi * 16 + (lane >> 2);
            int col = n0 + wn * 32 + ni * 8 + 2 * (lane & 3);
            if (col < 300) {
                float bc0 = bias[col], bc1 = bias[col + 1];
#pragma unroll
                for (int half = 0; half < 2; ++half) {
                    int r = row + half * 8;
                    float v0 = acc[mi][ni][2 * half] + bc0;
                    float v1 = acc[mi][ni][2 * half + 1] + bc1;
                    bf16 h0 = __float2bfloat16(v0), h1 = __float2bfloat16(v1);
                    u32 hp = ((u32)__bfloat16_as_ushort(h1) << 16) | __bfloat16_as_ushort(h0);
                    u32 lp = pk2(v1 - __bfloat162float(h1), v0 - __bfloat162float(h0));
                    *(u32*)&Whi[(size_t)r * KP + col] = hp;
                    *(u32*)&Wlo[(size_t)r * KP + col] = lp;
                }
            }
        }
}

// fused scores + softmax -> P fp16. CTA = 128 rows x full 512 w (two 256 halves)
__global__ __launch_bounds__(256) void scores_softmax_kernel() {
    extern __shared__ char sm[];
    const u32 sb = s2u(sm);
    const int tid = threadIdx.x, lane = tid & 31, wid = tid >> 5;
    const int wm = wid >> 2, wn = wid & 3;
    const int t0 = blockIdx.x * 128;
    const int b = blockIdx.z & 15, h = blockIdx.z >> 4, hb = h * 16 + b;
    float* red = (float*)(sm + RED_OFF);
    float* mA0 = (float*)(sm + MA0_OFF);
    float* sA0 = (float*)(sm + SA0_OFF);
    float* mA1 = (float*)(sm + MA1_OFF);
    float* sA1 = (float*)(sm + SA1_OFF);
    __half2* P0 = (__half2*)(sm + P0_OFF);
    __half2* P1 = (__half2*)(sm + P1_OFF);

    const bf16* Ah = g_Ahi + ((size_t)b * 2048 + t0) * KP;
    const bf16* Al = g_Alo + ((size_t)b * 2048 + t0) * KP;
    const bf16* Bh = g_Whi + (size_t)hb * 512 * KP;
    const bf16* Bl = g_Wlo + (size_t)hb * 512 * KP;

    float acc[4][8][4];

    // ---- half 0: w in [0,256)
    ACC_ZERO(acc, 4);
    gemm3<5, 4>(sb, Ah, Al, Bh, Bl, KP, acc);
    rowsoft(acc, red, mA0, sA0);
    // stage exp(s - m0) as fp16 (bank-swizzled)
#pragma unroll
    for (int mi = 0; mi < 4; ++mi)
#pragma unroll
        for (int ni = 0; ni < 8; ++ni)
#pragma unroll
            for (int h2 = 0; h2 < 2; ++h2) {
                int r = wm * 64 + mi * 16 + (lane >> 2) + h2 * 8;
                int w = wn * 32 + ni * 4 + (lane & 3);
                P0[r * 128 + (w ^ ((r & 7) << 2))] =
                    __floats2half2_rn(acc[mi][ni][2 * h2], acc[mi][ni][2 * h2 + 1]);
            }
    __syncthreads();

    // ---- half 1: w in [256,512)  (single-stage gemm; stage0 region only)
    ACC_ZERO(acc, 4);
    gemm3_1s<5, 4>(sb, Ah, Al, Bh + (size_t)256 * KP, Bl + (size_t)256 * KP, KP, acc);
    rowsoft(acc, red, mA1, sA1);

    // ---- merge scales
    if (tid < 128) {
        float m0 = mA0[tid], m1 = mA1[tid];
        float m = fmaxf(m0, m1);
        float e0 = __expf(m0 - m), e1 = __expf(m1 - m);
        float inv = 1.f / (sA0[tid] * e0 + sA1[tid] * e1);
        mA0[tid] = e0 * inv;   // scale0
        mA1[tid] = e1 * inv;   // scale1
    }
    __syncthreads();

    // stage half1 (scaled)
#pragma unroll
    for (int mi = 0; mi < 4; ++mi)
#pragma unroll
        for (int ni = 0; ni < 8; ++ni)
#pragma unroll
            for (int h2 = 0; h2 < 2; ++h2) {
                int r = wm * 64 + mi * 16 + (lane >> 2) + h2 * 8;
                int w = wn * 32 + ni * 4 + (lane & 3);
                float sc = mA1[r];
                P1[r * 128 + (w ^ ((r & 7) << 2))] =
                    __floats2half2_rn(acc[mi][ni][2 * h2] * sc, acc[mi][ni][2 * h2 + 1] * sc);
            }
    __syncthreads();

    // coalesced global writes of both halves
    __half2* Pg = (__half2*)(g_P16 + ((size_t)hb * 2048 + t0) * 512);
    for (int i = tid; i < 128 * 128; i += 256) {
        int r = i >> 7, w = i & 127;
        int ws = r * 128 + ((w ^ ((r & 7) << 2)));
        float sc0 = mA0[r];
        float2 f0 = __half22float2(P0[ws]);
        Pg[(size_t)r * 256 + w]       = __floats2half2_rn(f0.x * sc0, f0.y * sc0);
        Pg[(size_t)r * 256 + 128 + w] = P1[ws];
    }
}

// out = P @ V (single fp16 product), CTA 128x320, smem-staged stores
__global__ __launch_bounds__(256) void out_kernel(float* __restrict__ out) {
    extern __shared__ char sm[];
    const u32 sb = s2u(sm);
    const int tid = threadIdx.x;
    const int lane = tid & 31, wid = tid >> 5;
    const int wm = wid >> 2, wn = wid & 3;
    const int t0 = blockIdx.x * 128;
    const int b = blockIdx.z & 15, h = blockIdx.z >> 4, hb = h * 16 + b;
    float acc[4][10][4]; ACC_ZERO(acc, 5);
    gemm1<8, 5>(sb,
                (const bf16*)(g_P16 + ((size_t)hb * 2048 + t0) * 512),
                (const bf16*)(g_V16 + (size_t)b * 320 * 512),
                512, acc);
    float* stg = (float*)sm;
#pragma unroll
    for (int mi = 0; mi < 4; ++mi)
#pragma unroll
        for (int ni = 0; ni < 10; ++ni) {
            int r = wm * 64 + mi * 16 + (lane >> 2);
            int c = wn * 80 + ni * 8 + 2 * (lane & 3);
            *(float2*)&stg[r * 328 + c]       = make_float2(acc[mi][ni][0], acc[mi][ni][1]);
            *(float2*)&stg[(r + 8) * 328 + c] = make_float2(acc[mi][ni][2], acc[mi][ni][3]);
        }
    __syncthreads();
    for (int i = tid; i < 128 * 75; i += 256) {
        int r = i / 75, c = (i - r * 75) * 4;
        *(float4*)&out[((size_t)hb * 2048 + t0 + r) * 300 + c] = *(float4*)&stg[r * 328 + c];
    }
}

extern "C" void kernel_launch(void* const* d_in, const int* in_sizes, int n_in,
                              void* d_out, int out_size) {
    (void)in_sizes; (void)n_in; (void)out_size;
    const float* in1 = (const float*)d_in[0];
    const float* in2 = (const float*)d_in[1];
    const float* W2  = (const float*)d_in[2];
    const float* b2  = (const float*)d_in[3];
    const float* W3  = (const float*)d_in[4];
    const float* b3  = (const float*)d_in[5];
    float* out = (float*)d_out;

    split_in1<<<(int)((16L * 2048 * KP + 255) / 256), 256>>>(in1);
    split_in2<<<(int)((16L * 512 * KP + 255) / 256), 256>>>(in2);
    wsplit_kernel<<<(2 * 300 * 300 + 255) / 256, 256>>>(W2, W3);
    vt_kernel<<<dim3(16, 10, 16), dim3(32, 8)>>>(in2);

    cudaFuncSetAttribute(proj_mma, cudaFuncAttributeMaxDynamicSharedMemorySize, SMEM_GN2);
    proj_mma<<<dim3(64, 3, 2), 256, SMEM_GN2>>>(b2, b3);

    cudaFuncSetAttribute(scores_softmax_kernel, cudaFuncAttributeMaxDynamicSharedMemorySize, SMEM_SS);
    scores_softmax_kernel<<<dim3(16, 1, 32), 256, SMEM_SS>>>();

    cudaFuncSetAttribute(out_kernel, cudaFuncAttributeMaxDynamicSharedMemorySize, SMEM_OUT);
    out_kernel<<<dim3(16, 1, 32), 256, SMEM_OUT>>>(out);
}

// round 15
// speedup vs baseline: 1.0515x; 1.0515x over previous
#include <cuda_runtime.h>
#include <cuda_bf16.h>
#include <cuda_fp16.h>
#include <cstdint>

typedef unsigned long long ull;
typedef unsigned int u32;
typedef __nv_bfloat16 bf16;

// ---------- cp.async ----------
__device__ __forceinline__ void cpa16(u32 d, const void* s) {
    asm volatile("cp.async.cg.shared.global [%0], [%1], 16;" :: "r"(d), "l"(s));
}
#define CP_COMMIT() asm volatile("cp.async.commit_group;")
// ---------- mma.sync / ldmatrix ----------
__device__ __forceinline__ u32 s2u(const void* p) { return (u32)__cvta_generic_to_shared(p); }
__device__ __forceinline__ void ldsm4(u32* r, u32 a) {
    asm volatile("ldmatrix.sync.aligned.m8n8.x4.shared.b16 {%0,%1,%2,%3}, [%4];"
                 : "=r"(r[0]), "=r"(r[1]), "=r"(r[2]), "=r"(r[3]) : "r"(a));
}
__device__ __forceinline__ void mma16816(float* c, const u32* a, u32 b0, u32 b1) {
    asm volatile("mma.sync.aligned.m16n8k16.row.col.f32.bf16.bf16.f32 "
                 "{%0,%1,%2,%3}, {%4,%5,%6,%7}, {%8,%9}, {%0,%1,%2,%3};"
                 : "+f"(c[0]), "+f"(c[1]), "+f"(c[2]), "+f"(c[3])
                 : "r"(a[0]), "r"(a[1]), "r"(a[2]), "r"(a[3]), "r"(b0), "r"(b1));
}
__device__ __forceinline__ void mma16816h(float* c, const u32* a, u32 b0, u32 b1) {
    asm volatile("mma.sync.aligned.m16n8k16.row.col.f32.f16.f16.f32 "
                 "{%0,%1,%2,%3}, {%4,%5,%6,%7}, {%8,%9}, {%0,%1,%2,%3};"
                 : "+f"(c[0]), "+f"(c[1]), "+f"(c[2]), "+f"(c[3])
                 : "r"(a[0]), "r"(a[1]), "r"(a[2]), "r"(a[3]), "r"(b0), "r"(b1));
}
__device__ __forceinline__ u32 pk2(float up, float lo) {
    u32 d; asm("cvt.rn.bf16x2.f32 %0, %1, %2;" : "=r"(d) : "f"(up), "f"(lo)); return d;
}

#define KP 320
__device__ float g_S[2L * 16 * 2048 * 512];
__device__ bf16 g_Ahi[16L * 2048 * KP], g_Alo[16L * 2048 * KP];
__device__ bf16 g_I2hi[16L * 512 * KP], g_I2lo[16L * 512 * KP];
__device__ bf16 g_Wsphi[2L * 384 * KP], g_Wsplo[2L * 384 * KP];       // pads zero-init
__device__ bf16 g_Whi[2L * 16 * 512 * KP], g_Wlo[2L * 16 * 512 * KP]; // cols>=300 zero-init
__device__ __half g_V16[16L * 320 * 512];                              // rows 300..319 zero-init
__device__ __half g_P16[2L * 16 * 2048 * 512];

// stage rows x 64-col 16-bit tile (128B rows), XOR swizzle; 256 threads
__device__ __forceinline__ void ldt(u32 dst, const bf16* src, int pitch, int k0, int rows) {
    for (int i = threadIdx.x; i < rows * 8; i += 256) {
        int r = i >> 3, c = i & 7;
        cpa16(dst + r * 128 + ((c ^ (r & 7)) << 4), src + (size_t)r * pitch + k0 + c * 8);
    }
}

__global__ void split_in1(const float* __restrict__ in1) {
    size_t i = (size_t)blockIdx.x * 256 + threadIdx.x;
    if (i >= 16L * 2048 * KP) return;
    int k = (int)(i % KP); size_t bt = i / KP;
    float v = (k < 300) ? in1[bt * 300 + k] : 0.f;
    bf16 h = __float2bfloat16(v);
    g_Ahi[i] = h; g_Alo[i] = __float2bfloat16(v - __bfloat162float(h));
}

__global__ void split_in2(const float* __restrict__ in2) {
    size_t i = (size_t)blockIdx.x * 256 + threadIdx.x;
    if (i >= 16L * 512 * KP) return;
    int k = (int)(i % KP); size_t bw = i / KP;
    float v = (k < 300) ? in2[bw * 300 + k] : 0.f;
    bf16 h = __float2bfloat16(v);
    g_I2hi[i] = h; g_I2lo[i] = __float2bfloat16(v - __bfloat162float(h));
}

__global__ void wsplit_kernel(const float* __restrict__ W2, const float* __restrict__ W3) {
    int idx = blockIdx.x * blockDim.x + threadIdx.x;
    if (idx >= 2 * 300 * 300) return;
    int h = idx / (300 * 300), rem = idx - h * (300 * 300);
    int e = rem / 300, d = rem - e * 300;
    float v = (h ? W3 : W2)[e * 300 + d];
    bf16 hi = __float2bfloat16(v);
    size_t o = ((size_t)h * 384 + e) * KP + d;
    g_Wsphi[o] = hi; g_Wsplo[o] = __float2bfloat16(v - __bfloat162float(hi));
}

// V16[b][d][w] = fp16(in2[b][w][d]), d in [0,320), rows >=300 left zero
__global__ void vt_kernel(const float* __restrict__ in2) {
    __shared__ float t[32][33];
    const int b = blockIdx.z, d0 = blockIdx.y * 32, w0 = blockIdx.x * 32;
    const int tx = threadIdx.x, ty = threadIdx.y;
    for (int yy = ty; yy < 32; yy += 8)
        t[yy][tx] = (d0 + tx < 300) ? in2[((size_t)b * 512 + w0 + yy) * 300 + d0 + tx] : 0.f;
    __syncthreads();
    for (int yy = ty; yy < 32; yy += 8)
        g_V16[((size_t)b * 320 + d0 + yy) * 512 + w0 + tx] = __float2half(t[tx][yy]);
}

// ========== 3-product bf16 GEMM core, 2-stage ==========
template<int NCHUNK, int GN>
__device__ __forceinline__ void gemm3(u32 sb, const bf16* Ah, const bf16* Al,
                                      const bf16* Bh, const bf16* Bl,
                                      int pitch, float acc[4][2 * GN][4]) {
    constexpr int BN = 64 * GN;
    constexpr u32 ASZ = 128 * 128;
    constexpr u32 BSZ = (u32)BN * 128;
    constexpr u32 STAGE = 2 * ASZ + 2 * BSZ;
    const int lane = threadIdx.x & 31, wid = threadIdx.x >> 5;
    const int wm = wid >> 2, wn = wid & 3;
    ldt(sb, Ah, pitch, 0, 128);             ldt(sb + ASZ, Al, pitch, 0, 128);
    ldt(sb + 2 * ASZ, Bh, pitch, 0, BN);    ldt(sb + 2 * ASZ + BSZ, Bl, pitch, 0, BN);
    CP_COMMIT();
    const int rA = wm * 64 + (lane & 15), rB = wn * (GN * 16) + (lane & 15);
    const int chalf = lane >> 4;
    for (int kc = 0; kc < NCHUNK; ++kc) {
        if (kc + 1 < NCHUNK) {
            u32 d = sb + ((kc + 1) & 1) * STAGE;
            int k0 = (kc + 1) * 64;
            ldt(d, Ah, pitch, k0, 128);          ldt(d + ASZ, Al, pitch, k0, 128);
            ldt(d + 2 * ASZ, Bh, pitch, k0, BN); ldt(d + 2 * ASZ + BSZ, Bl, pitch, k0, BN);
            CP_COMMIT();
            asm volatile("cp.async.wait_group 1;");
        } else {
            asm volatile("cp.async.wait_group 0;");
        }
        __syncthreads();
        u32 st = sb + (kc & 1) * STAGE;
#pragma unroll
        for (int ks = 0; ks < 4; ++ks) {
            const int c16 = ks * 2 + chalf;
            const u32 offA = rA * 128 + (((u32)(c16 ^ (rA & 7))) << 4);
            const u32 offB = rB * 128 + (((u32)(c16 ^ (rB & 7))) << 4);
            u32 ah[4][4], al[4][4], bh[GN][4], bl[GN][4];
#pragma unroll
            for (int mi = 0; mi < 4; ++mi) {
                ldsm4(ah[mi], st + offA + mi * 2048);
                ldsm4(al[mi], st + ASZ + offA + mi * 2048);
            }
#pragma unroll
            for (int g = 0; g < GN; ++g) {
                ldsm4(bh[g], st + 2 * ASZ + offB + g * 2048);
                ldsm4(bl[g], st + 2 * ASZ + BSZ + offB + g * 2048);
            }
#pragma unroll
            for (int mi = 0; mi < 4; ++mi)
#pragma unroll
                for (int g = 0; g < GN; ++g)
#pragma unroll
                    for (int sub = 0; sub < 2; ++sub) {
                        float* c = acc[mi][g * 2 + sub];
                        mma16816(c, ah[mi], bh[g][sub], bh[g][sub + 2]);
                        mma16816(c, ah[mi], bl[g][sub], bl[g][sub + 2]);
                        mma16816(c, al[mi], bh[g][sub], bh[g][sub + 2]);
                    }
        }
        __syncthreads();
    }
}

// ========== single-product fp16 GEMM core (out), 2-stage ==========
template<int NCHUNK, int GN>
__device__ __forceinline__ void gemm1(u32 sb, const bf16* A, const bf16* B,
                                      int pitch, float acc[4][2 * GN][4]) {
    constexpr int BN = 64 * GN;
    constexpr u32 ASZ = 128 * 128;
    constexpr u32 BSZ = (u32)BN * 128;
    constexpr u32 STAGE = ASZ + BSZ;
    const int lane = threadIdx.x & 31, wid = threadIdx.x >> 5;
    const int wm = wid >> 2, wn = wid & 3;
    ldt(sb, A, pitch, 0, 128);
    ldt(sb + ASZ, B, pitch, 0, BN);
    CP_COMMIT();
    const int rA = wm * 64 + (lane & 15), rB = wn * (GN * 16) + (lane & 15);
    const int chalf = lane >> 4;
    for (int kc = 0; kc < NCHUNK; ++kc) {
        if (kc + 1 < NCHUNK) {
            u32 d = sb + ((kc + 1) & 1) * STAGE;
            int k0 = (kc + 1) * 64;
            ldt(d, A, pitch, k0, 128);
            ldt(d + ASZ, B, pitch, k0, BN);
            CP_COMMIT();
            asm volatile("cp.async.wait_group 1;");
        } else {
            asm volatile("cp.async.wait_group 0;");
        }
        __syncthreads();
        u32 st = sb + (kc & 1) * STAGE;
#pragma unroll
        for (int ks = 0; ks < 4; ++ks) {
            const int c16 = ks * 2 + chalf;
            const u32 offA = rA * 128 + (((u32)(c16 ^ (rA & 7))) << 4);
            const u32 offB = rB * 128 + (((u32)(c16 ^ (rB & 7))) << 4);
            u32 ah[4][4], bh[GN][4];
#pragma unroll
            for (int mi = 0; mi < 4; ++mi) ldsm4(ah[mi], st + offA + mi * 2048);
#pragma unroll
            for (int g = 0; g < GN; ++g)  ldsm4(bh[g], st + ASZ + offB + g * 2048);
#pragma unroll
            for (int mi = 0; mi < 4; ++mi)
#pragma unroll
                for (int g = 0; g < GN; ++g)
#pragma unroll
                    for (int sub = 0; sub < 2; ++sub)
                        mma16816h(acc[mi][g * 2 + sub], ah[mi], bh[g][sub], bh[g][sub + 2]);
        }
        __syncthreads();
    }
}

#define SMEM_GN4 196608
#define SMEM_GN2 131072
#define SMEM_OUT 172032
#define ACC_ZERO(acc, GN) do { _Pragma("unroll") for (int _i = 0; _i < 4; ++_i) \
    _Pragma("unroll") for (int _j = 0; _j < 2 * (GN); ++_j) \
    _Pragma("unroll") for (int _q = 0; _q < 4; ++_q) acc[_i][_j][_q] = 0.f; } while (0)

// proj = in2 @ W^T + b -> g_Whi/g_Wlo ([h*8192 + b*512 + w][e])
__global__ __launch_bounds__(256) void proj_mma(const float* __restrict__ b2,
                                                const float* __restrict__ b3) {
    extern __shared__ char sm[];
    const u32 sb = s2u(sm);
    const int lane = threadIdx.x & 31, wid = threadIdx.x >> 5;
    const int wm = wid >> 2, wn = wid & 3;
    const int t0 = blockIdx.x * 128, n0 = blockIdx.y * 128, h = blockIdx.z;
    float acc[4][4][4]; ACC_ZERO(acc, 2);
    gemm3<5, 2>(sb, g_I2hi + (size_t)t0 * KP, g_I2lo + (size_t)t0 * KP,
                g_Wsphi + ((size_t)h * 384 + n0) * KP, g_Wsplo + ((size_t)h * 384 + n0) * KP,
                KP, acc);
    const float* bias = h ? b3 : b2;
    bf16* Whi = g_Whi + (size_t)h * 8192 * KP;
    bf16* Wlo = g_Wlo + (size_t)h * 8192 * KP;
#pragma unroll
    for (int mi = 0; mi < 4; ++mi)
#pragma unroll
        for (int ni = 0; ni < 4; ++ni) {
            int row = t0 + wm * 64 + mi * 16 + (lane >> 2);
            int col = n0 + wn * 32 + ni * 8 + 2 * (lane & 3);
            if (col < 300) {
                float bc0 = bias[col], bc1 = bias[col + 1];
#pragma unroll
                for (int half = 0; half < 2; ++half) {
                    int r = row + half * 8;
                    float v0 = acc[mi][ni][2 * half] + bc0;
                    float v1 = acc[mi][ni][2 * half + 1] + bc1;
                    bf16 h0 = __float2bfloat16(v0), h1 = __float2bfloat16(v1);
                    u32 hp = ((u32)__bfloat16_as_ushort(h1) << 16) | __bfloat16_as_ushort(h0);
                    u32 lp = pk2(v1 - __bfloat162float(h1), v0 - __bfloat162float(h0));
                    *(u32*)&Whi[(size_t)r * KP + col] = hp;
                    *(u32*)&Wlo[(size_t)r * KP + col] = lp;
                }
            }
        }
}

// scores: S[t][w] fp32, CTA 128x256, smem-staged coalesced stores
__global__ __launch_bounds__(256) void scores_kernel() {
    extern __shared__ char sm[];
    const u32 sb = s2u(sm);
    const int tid = threadIdx.x;
    const int lane = tid & 31, wid = tid >> 5;
    const int wm = wid >> 2, wn = wid & 3;
    const int t0 = blockIdx.x * 128, w0 = blockIdx.y * 256;
    const int b = blockIdx.z & 15, h = blockIdx.z >> 4, hb = h * 16 + b;
    float acc[4][8][4]; ACC_ZERO(acc, 4);
    gemm3<5, 4>(sb,
                g_Ahi + ((size_t)b * 2048 + t0) * KP, g_Alo + ((size_t)b * 2048 + t0) * KP,
                g_Whi + ((size_t)hb * 512 + w0) * KP, g_Wlo + ((size_t)hb * 512 + w0) * KP,
                KP, acc);
    float* stg = (float*)sm;
#pragma unroll
    for (int mi = 0; mi < 4; ++mi)
#pragma unroll
        for (int ni = 0; ni < 8; ++ni) {
            int r = wm * 64 + mi * 16 + (lane >> 2);
            int c = wn * 64 + ni * 8 + 2 * (lane & 3);
            *(float2*)&stg[r * 264 + c]       = make_float2(acc[mi][ni][0], acc[mi][ni][1]);
            *(float2*)&stg[(r + 8) * 264 + c] = make_float2(acc[mi][ni][2], acc[mi][ni][3]);
        }
    __syncthreads();
    float* S = g_S + (size_t)hb * 2048 * 512;
    for (int i = tid; i < 128 * 64; i += 256) {
        int r = i >> 6, c4 = (i & 63) * 4;
        *(float4*)&S[(size_t)(t0 + r) * 512 + w0 + c4] = *(float4*)&stg[r * 264 + c4];
    }
}

// softmax: warp per row -> P fp16
__global__ __launch_bounds__(256) void softmax_kernel() {
    const int lane = threadIdx.x & 31;
    const size_t R = (size_t)blockIdx.x * 8 + (threadIdx.x >> 5);
    const float4* Srow = (const float4*)(g_S + R * 512);
    float v[16];
#pragma unroll
    for (int i = 0; i < 4; ++i) {
        float4 q = Srow[i * 32 + lane];
        v[4 * i] = q.x; v[4 * i + 1] = q.y; v[4 * i + 2] = q.z; v[4 * i + 3] = q.w;
    }
    float m = v[0];
#pragma unroll
    for (int i = 1; i < 16; ++i) m = fmaxf(m, v[i]);
#pragma unroll
    for (int o = 16; o; o >>= 1) m = fmaxf(m, __shfl_xor_sync(0xffffffffu, m, o));
    float s = 0.f;
#pragma unroll
    for (int i = 0; i < 16; ++i) { v[i] = __expf(v[i] - m); s += v[i]; }
#pragma unroll
    for (int o = 16; o; o >>= 1) s += __shfl_xor_sync(0xffffffffu, s, o);
    const float inv = 1.f / s;
    __half2* P = (__half2*)(g_P16 + R * 512);
#pragma unroll
    for (int i = 0; i < 4; ++i) {
        int base = (i * 32 + lane) * 2;
        P[base]     = __floats2half2_rn(v[4 * i] * inv,     v[4 * i + 1] * inv);
        P[base + 1] = __floats2half2_rn(v[4 * i + 2] * inv, v[4 * i + 3] * inv);
    }
}

// out = P @ V (single fp16 product), CTA 128x320, smem-staged stores
__global__ __launch_bounds__(256) void out_kernel(float* __restrict__ out) {
    extern __shared__ char sm[];
    const u32 sb = s2u(sm);
    const int tid = threadIdx.x;
    const int lane = tid & 31, wid = tid >> 5;
    const int wm = wid >> 2, wn = wid & 3;
    const int t0 = blockIdx.x * 128;
    const int b = blockIdx.z & 15, h = blockIdx.z >> 4, hb = h * 16 + b;
    float acc[4][10][4]; ACC_ZERO(acc, 5);
    gemm1<8, 5>(sb,
                (const bf16*)(g_P16 + ((size_t)hb * 2048 + t0) * 512),
                (const bf16*)(g_V16 + (size_t)b * 320 * 512),
                512, acc);
    float* stg = (float*)sm;
#pragma unroll
    for (int mi = 0; mi < 4; ++mi)
#pragma unroll
        for (int ni = 0; ni < 10; ++ni) {
            int r = wm * 64 + mi * 16 + (lane >> 2);
            int c = wn * 80 + ni * 8 + 2 * (lane & 3);
            *(float2*)&stg[r * 328 + c]       = make_float2(acc[mi][ni][0], acc[mi][ni][1]);
            *(float2*)&stg[(r + 8) * 328 + c] = make_float2(acc[mi][ni][2], acc[mi][ni][3]);
        }
    __syncthreads();
    for (int i = tid; i < 128 * 75; i += 256) {
        int r = i / 75, c = (i - r * 75) * 4;
        *(float4*)&out[((size_t)hb * 2048 + t0 + r) * 300 + c] = *(float4*)&stg[r * 328 + c];
    }
}

extern "C" void kernel_launch(void* const* d_in, const int* in_sizes, int n_in,
                              void* d_out, int out_size) {
    (void)in_sizes; (void)n_in; (void)out_size;
    const float* in1 = (const float*)d_in[0];
    const float* in2 = (const float*)d_in[1];
    const float* W2  = (const float*)d_in[2];
    const float* b2  = (const float*)d_in[3];
    const float* W3  = (const float*)d_in[4];
    const float* b3  = (const float*)d_in[5];
    float* out = (float*)d_out;

    // one-time setup on the (non-captured) correctness call; reused during capture
    static bool inited = false;
    static cudaStream_t s1, s2;
    static cudaEvent_t eFork, e1, e2;
    if (!inited) {
        cudaStreamCreateWithFlags(&s1, cudaStreamNonBlocking);
        cudaStreamCreateWithFlags(&s2, cudaStreamNonBlocking);
        cudaEventCreateWithFlags(&eFork, cudaEventDisableTiming);
        cudaEventCreateWithFlags(&e1, cudaEventDisableTiming);
        cudaEventCreateWithFlags(&e2, cudaEventDisableTiming);
        cudaFuncSetAttribute(proj_mma, cudaFuncAttributeMaxDynamicSharedMemorySize, SMEM_GN2);
        cudaFuncSetAttribute(scores_kernel, cudaFuncAttributeMaxDynamicSharedMemorySize, SMEM_GN4);
        cudaFuncSetAttribute(out_kernel, cudaFuncAttributeMaxDynamicSharedMemorySize, SMEM_OUT);
        inited = true;
    }

    // fork: branch1 = proj chain (s1), branch2 = vt (s2), main = split_in1
    cudaEventRecord(eFork, 0);
    cudaStreamWaitEvent(s1, eFork, 0);
    cudaStreamWaitEvent(s2, eFork, 0);

    split_in1<<<(int)((16L * 2048 * KP + 255) / 256), 256>>>(in1);

    split_in2<<<(int)((16L * 512 * KP + 255) / 256), 256, 0, s1>>>(in2);
    wsplit_kernel<<<(2 * 300 * 300 + 255) / 256, 256, 0, s1>>>(W2, W3);
    proj_mma<<<dim3(64, 3, 2), 256, SMEM_GN2, s1>>>(b2, b3);
    cudaEventRecord(e1, s1);

    vt_kernel<<<dim3(16, 10, 16), dim3(32, 8), 0, s2>>>(in2);
    cudaEventRecord(e2, s2);

    // join before scores (needs split_in1 + proj); vt joins too (needed by out)
    cudaStreamWaitEvent(0, e1, 0);
    cudaStreamWaitEvent(0, e2, 0);

    scores_kernel<<<dim3(16, 2, 32), 256, SMEM_GN4>>>();
    softmax_kernel<<<8192, 256>>>();
    out_kernel<<<dim3(16, 1, 32), 256, SMEM_OUT>>>(out);
}

// round 16
// speedup vs baseline: 1.0692x; 1.0169x over previous
#include <cuda_runtime.h>
#include <cuda_bf16.h>
#include <cuda_fp16.h>
#include <cstdint>

typedef unsigned long long ull;
typedef unsigned int u32;
typedef __nv_bfloat16 bf16;

// ---------- cp.async ----------
__device__ __forceinline__ void cpa16(u32 d, const void* s) {
    asm volatile("cp.async.cg.shared.global [%0], [%1], 16;" :: "r"(d), "l"(s));
}
#define CP_COMMIT() asm volatile("cp.async.commit_group;")
// ---------- mma.sync / ldmatrix ----------
__device__ __forceinline__ u32 s2u(const void* p) { return (u32)__cvta_generic_to_shared(p); }
__device__ __forceinline__ void ldsm4(u32* r, u32 a) {
    asm volatile("ldmatrix.sync.aligned.m8n8.x4.shared.b16 {%0,%1,%2,%3}, [%4];"
                 : "=r"(r[0]), "=r"(r[1]), "=r"(r[2]), "=r"(r[3]) : "r"(a));
}
__device__ __forceinline__ void mma16816(float* c, const u32* a, u32 b0, u32 b1) {
    asm volatile("mma.sync.aligned.m16n8k16.row.col.f32.bf16.bf16.f32 "
                 "{%0,%1,%2,%3}, {%4,%5,%6,%7}, {%8,%9}, {%0,%1,%2,%3};"
                 : "+f"(c[0]), "+f"(c[1]), "+f"(c[2]), "+f"(c[3])
                 : "r"(a[0]), "r"(a[1]), "r"(a[2]), "r"(a[3]), "r"(b0), "r"(b1));
}
__device__ __forceinline__ void mma16816h(float* c, const u32* a, u32 b0, u32 b1) {
    asm volatile("mma.sync.aligned.m16n8k16.row.col.f32.f16.f16.f32 "
                 "{%0,%1,%2,%3}, {%4,%5,%6,%7}, {%8,%9}, {%0,%1,%2,%3};"
                 : "+f"(c[0]), "+f"(c[1]), "+f"(c[2]), "+f"(c[3])
                 : "r"(a[0]), "r"(a[1]), "r"(a[2]), "r"(a[3]), "r"(b0), "r"(b1));
}
__device__ __forceinline__ u32 pk2(float up, float lo) {
    u32 d; asm("cvt.rn.bf16x2.f32 %0, %1, %2;" : "=r"(d) : "f"(up), "f"(lo)); return d;
}

#define KP 320
__device__ float g_S[2L * 16 * 2048 * 512];
__device__ bf16 g_Ahi[16L * 2048 * KP], g_Alo[16L * 2048 * KP];
__device__ bf16 g_I2hi[16L * 512 * KP], g_I2lo[16L * 512 * KP];
__device__ bf16 g_Wsphi[2L * 384 * KP], g_Wsplo[2L * 384 * KP];       // pads zero-init
__device__ bf16 g_Whi[2L * 16 * 512 * KP], g_Wlo[2L * 16 * 512 * KP]; // cols>=300 zero-init
__device__ __half g_V16[16L * 320 * 512];                              // rows 300..319 zero-init
__device__ __half g_P16[2L * 16 * 2048 * 512];

// stage rows x 64-col 16-bit tile (128B rows), XOR swizzle; 256 threads
__device__ __forceinline__ void ldt(u32 dst, const bf16* src, int pitch, int k0, int rows) {
    for (int i = threadIdx.x; i < rows * 8; i += 256) {
        int r = i >> 3, c = i & 7;
        cpa16(dst + r * 128 + ((c ^ (r & 7)) << 4), src + (size_t)r * pitch + k0 + c * 8);
    }
}

__global__ void split_in1(const float* __restrict__ in1) {
    size_t i = (size_t)blockIdx.x * 256 + threadIdx.x;
    if (i >= 16L * 2048 * KP) return;
    int k = (int)(i % KP); size_t bt = i / KP;
    float v = (k < 300) ? in1[bt * 300 + k] : 0.f;
    bf16 h = __float2bfloat16(v);
    g_Ahi[i] = h; g_Alo[i] = __float2bfloat16(v - __bfloat162float(h));
}

__global__ void split_in2(const float* __restrict__ in2) {
    size_t i = (size_t)blockIdx.x * 256 + threadIdx.x;
    if (i >= 16L * 512 * KP) return;
    int k = (int)(i % KP); size_t bw = i / KP;
    float v = (k < 300) ? in2[bw * 300 + k] : 0.f;
    bf16 h = __float2bfloat16(v);
    g_I2hi[i] = h; g_I2lo[i] = __float2bfloat16(v - __bfloat162float(h));
}

__global__ void wsplit_kernel(const float* __restrict__ W2, const float* __restrict__ W3) {
    int idx = blockIdx.x * blockDim.x + threadIdx.x;
    if (idx >= 2 * 300 * 300) return;
    int h = idx / (300 * 300), rem = idx - h * (300 * 300);
    int e = rem / 300, d = rem - e * 300;
    float v = (h ? W3 : W2)[e * 300 + d];
    bf16 hi = __float2bfloat16(v);
    size_t o = ((size_t)h * 384 + e) * KP + d;
    g_Wsphi[o] = hi; g_Wsplo[o] = __float2bfloat16(v - __bfloat162float(hi));
}

// V16[b][d][w] = fp16(in2[b][w][d])
__global__ void vt_kernel(const float* __restrict__ in2) {
    __shared__ float t[32][33];
    const int b = blockIdx.z, d0 = blockIdx.y * 32, w0 = blockIdx.x * 32;
    const int tx = threadIdx.x, ty = threadIdx.y;
    for (int yy = ty; yy < 32; yy += 8)
        t[yy][tx] = (d0 + tx < 300) ? in2[((size_t)b * 512 + w0 + yy) * 300 + d0 + tx] : 0.f;
    __syncthreads();
    for (int yy = ty; yy < 32; yy += 8)
        g_V16[((size_t)b * 320 + d0 + yy) * 512 + w0 + tx] = __float2half(t[tx][yy]);
}

// ========== 3-product bf16 GEMM core, 2-stage ==========
template<int NCHUNK, int GN>
__device__ __forceinline__ void gemm3(u32 sb, const bf16* Ah, const bf16* Al,
                                      const bf16* Bh, const bf16* Bl,
                                      int pitch, float acc[4][2 * GN][4]) {
    constexpr int BN = 64 * GN;
    constexpr u32 ASZ = 128 * 128;
    constexpr u32 BSZ = (u32)BN * 128;
    constexpr u32 STAGE = 2 * ASZ + 2 * BSZ;
    const int lane = threadIdx.x & 31, wid = threadIdx.x >> 5;
    const int wm = wid >> 2, wn = wid & 3;
    ldt(sb, Ah, pitch, 0, 128);             ldt(sb + ASZ, Al, pitch, 0, 128);
    ldt(sb + 2 * ASZ, Bh, pitch, 0, BN);    ldt(sb + 2 * ASZ + BSZ, Bl, pitch, 0, BN);
    CP_COMMIT();
    const int rA = wm * 64 + (lane & 15), rB = wn * (GN * 16) + (lane & 15);
    const int chalf = lane >> 4;
    for (int kc = 0; kc < NCHUNK; ++kc) {
        if (kc + 1 < NCHUNK) {
            u32 d = sb + ((kc + 1) & 1) * STAGE;
            int k0 = (kc + 1) * 64;
            ldt(d, Ah, pitch, k0, 128);          ldt(d + ASZ, Al, pitch, k0, 128);
            ldt(d + 2 * ASZ, Bh, pitch, k0, BN); ldt(d + 2 * ASZ + BSZ, Bl, pitch, k0, BN);
            CP_COMMIT();
            asm volatile("cp.async.wait_group 1;");
        } else {
            asm volatile("cp.async.wait_group 0;");
        }
        __syncthreads();
        u32 st = sb + (kc & 1) * STAGE;
#pragma unroll
        for (int ks = 0; ks < 4; ++ks) {
            const int c16 = ks * 2 + chalf;
            const u32 offA = rA * 128 + (((u32)(c16 ^ (rA & 7))) << 4);
            const u32 offB = rB * 128 + (((u32)(c16 ^ (rB & 7))) << 4);
            u32 ah[4][4], al[4][4], bh[GN][4], bl[GN][4];
#pragma unroll
            for (int mi = 0; mi < 4; ++mi) {
                ldsm4(ah[mi], st + offA + mi * 2048);
                ldsm4(al[mi], st + ASZ + offA + mi * 2048);
            }
#pragma unroll
            for (int g = 0; g < GN; ++g) {
                ldsm4(bh[g], st + 2 * ASZ + offB + g * 2048);
                ldsm4(bl[g], st + 2 * ASZ + BSZ + offB + g * 2048);
            }
#pragma unroll
            for (int mi = 0; mi < 4; ++mi)
#pragma unroll
                for (int g = 0; g < GN; ++g)
#pragma unroll
                    for (int sub = 0; sub < 2; ++sub) {
                        float* c = acc[mi][g * 2 + sub];
                        mma16816(c, ah[mi], bh[g][sub], bh[g][sub + 2]);
                        mma16816(c, ah[mi], bl[g][sub], bl[g][sub + 2]);
                        mma16816(c, al[mi], bh[g][sub], bh[g][sub + 2]);
                    }
        }
        __syncthreads();
    }
}

// ========== single-product fp16 GEMM core (out), 3-stage ==========
template<int NCHUNK, int GN>
__device__ __forceinline__ void gemm1(u32 sb, const bf16* A, const bf16* B,
                                      int pitch, float acc[4][2 * GN][4]) {
    constexpr int BN = 64 * GN;
    constexpr u32 ASZ = 128 * 128;
    constexpr u32 BSZ = (u32)BN * 128;
    constexpr u32 STAGE = ASZ + BSZ;
    const int lane = threadIdx.x & 31, wid = threadIdx.x >> 5;
    const int wm = wid >> 2, wn = wid & 3;
    ldt(sb, A, pitch, 0, 128);                 ldt(sb + ASZ, B, pitch, 0, BN);
    CP_COMMIT();
    ldt(sb + STAGE, A, pitch, 64, 128);        ldt(sb + STAGE + ASZ, B, pitch, 64, BN);
    CP_COMMIT();
    const int rA = wm * 64 + (lane & 15), rB = wn * (GN * 16) + (lane & 15);
    const int chalf = lane >> 4;
    for (int kc = 0; kc < NCHUNK; ++kc) {
        if (kc + 2 < NCHUNK) {
            u32 d = sb + ((kc + 2) % 3) * STAGE;
            int k0 = (kc + 2) * 64;
            ldt(d, A, pitch, k0, 128);
            ldt(d + ASZ, B, pitch, k0, BN);
            CP_COMMIT();
            asm volatile("cp.async.wait_group 2;");
        } else if (kc + 1 < NCHUNK) {
            asm volatile("cp.async.wait_group 1;");
        } else {
            asm volatile("cp.async.wait_group 0;");
        }
        __syncthreads();
        u32 st = sb + (kc % 3) * STAGE;
#pragma unroll
        for (int ks = 0; ks < 4; ++ks) {
            const int c16 = ks * 2 + chalf;
            const u32 offA = rA * 128 + (((u32)(c16 ^ (rA & 7))) << 4);
            const u32 offB = rB * 128 + (((u32)(c16 ^ (rB & 7))) << 4);
            u32 ah[4][4], bh[GN][4];
#pragma unroll
            for (int mi = 0; mi < 4; ++mi) ldsm4(ah[mi], st + offA + mi * 2048);
#pragma unroll
            for (int g = 0; g < GN; ++g)  ldsm4(bh[g], st + ASZ + offB + g * 2048);
#pragma unroll
            for (int mi = 0; mi < 4; ++mi)
#pragma unroll
                for (int g = 0; g < GN; ++g)
#pragma unroll
                    for (int sub = 0; sub < 2; ++sub)
                        mma16816h(acc[mi][g * 2 + sub], ah[mi], bh[g][sub], bh[g][sub + 2]);
        }
        __syncthreads();
    }
}

#define SMEM_GN4 196608
#define SMEM_PROJ 98304   // GN1: 2 x 48KB -> 2 CTAs/SM
#define SMEM_OUT 172032   // 3 x 56KB mainloop; 164KB epilogue staging
#define ACC_ZERO(acc, GN) do { _Pragma("unroll") for (int _i = 0; _i < 4; ++_i) \
    _Pragma("unroll") for (int _j = 0; _j < 2 * (GN); ++_j) \
    _Pragma("unroll") for (int _q = 0; _q < 4; ++_q) acc[_i][_j][_q] = 0.f; } while (0)

// proj = in2 @ W^T + b -> g_Whi/g_Wlo ([h*8192 + b*512 + w][e]); GN1 tiles, 2 CTAs/SM
__global__ __launch_bounds__(256, 2) void proj_mma(const float* __restrict__ b2,
                                                   const float* __restrict__ b3) {
    extern __shared__ char sm[];
    const u32 sb = s2u(sm);
    const int lane = threadIdx.x & 31, wid = threadIdx.x >> 5;
    const int wm = wid >> 2, wn = wid & 3;
    const int t0 = blockIdx.x * 128, n0 = blockIdx.y * 64, h = blockIdx.z;
    float acc[4][2][4]; ACC_ZERO(acc, 1);
    gemm3<5, 1>(sb, g_I2hi + (size_t)t0 * KP, g_I2lo + (size_t)t0 * KP,
                g_Wsphi + ((size_t)h * 384 + n0) * KP, g_Wsplo + ((size_t)h * 384 + n0) * KP,
                KP, acc);
    const float* bias = h ? b3 : b2;
    bf16* Whi = g_Whi + (size_t)h * 8192 * KP;
    bf16* Wlo = g_Wlo + (size_t)h * 8192 * KP;
#pragma unroll
    for (int mi = 0; mi < 4; ++mi)
#pragma unroll
        for (int ni = 0; ni < 2; ++ni) {
            int row = t0 + wm * 64 + mi * 16 + (lane >> 2);
            int col = n0 + wn * 16 + ni * 8 + 2 * (lane & 3);
            if (col < 300) {
                float bc0 = bias[col], bc1 = bias[col + 1];
#pragma unroll
                for (int half = 0; half < 2; ++half) {
                    int r = row + half * 8;
                    float v0 = acc[mi][ni][2 * half] + bc0;
                    float v1 = acc[mi][ni][2 * half + 1] + bc1;
                    bf16 h0 = __float2bfloat16(v0), h1 = __float2bfloat16(v1);
                    u32 hp = ((u32)__bfloat16_as_ushort(h1) << 16) | __bfloat16_as_ushort(h0);
                    u32 lp = pk2(v1 - __bfloat162float(h1), v0 - __bfloat162float(h0));
                    *(u32*)&Whi[(size_t)r * KP + col] = hp;
                    *(u32*)&Wlo[(size_t)r * KP + col] = lp;
                }
            }
        }
}

// scores: S[t][w] fp32, CTA 128x256, smem-staged coalesced stores
__global__ __launch_bounds__(256) void scores_kernel() {
    extern __shared__ char sm[];
    const u32 sb = s2u(sm);
    const int tid = threadIdx.x;
    const int lane = tid & 31, wid = tid >> 5;
    const int wm = wid >> 2, wn = wid & 3;
    const int t0 = blockIdx.x * 128, w0 = blockIdx.y * 256;
    const int b = blockIdx.z & 15, h = blockIdx.z >> 4, hb = h * 16 + b;
    float acc[4][8][4]; ACC_ZERO(acc, 4);
    gemm3<5, 4>(sb,
                g_Ahi + ((size_t)b * 2048 + t0) * KP, g_Alo + ((size_t)b * 2048 + t0) * KP,
                g_Whi + ((size_t)hb * 512 + w0) * KP, g_Wlo + ((size_t)hb * 512 + w0) * KP,
                KP, acc);
    float* stg = (float*)sm;
#pragma unroll
    for (int mi = 0; mi < 4; ++mi)
#pragma unroll
        for (int ni = 0; ni < 8; ++ni) {
            int r = wm * 64 + mi * 16 + (lane >> 2);
            int c = wn * 64 + ni * 8 + 2 * (lane & 3);
            *(float2*)&stg[r * 264 + c]       = make_float2(acc[mi][ni][0], acc[mi][ni][1]);
            *(float2*)&stg[(r + 8) * 264 + c] = make_float2(acc[mi][ni][2], acc[mi][ni][3]);
        }
    __syncthreads();
    float* S = g_S + (size_t)hb * 2048 * 512;
    for (int i = tid; i < 128 * 64; i += 256) {
        int r = i >> 6, c4 = (i & 63) * 4;
        *(float4*)&S[(size_t)(t0 + r) * 512 + w0 + c4] = *(float4*)&stg[r * 264 + c4];
    }
}

// softmax: warp per row -> P fp16
__global__ __launch_bounds__(256) void softmax_kernel() {
    const int lane = threadIdx.x & 31;
    const size_t R = (size_t)blockIdx.x * 8 + (threadIdx.x >> 5);
    const float4* Srow = (const float4*)(g_S + R * 512);
    float v[16];
#pragma unroll
    for (int i = 0; i < 4; ++i) {
        float4 q = Srow[i * 32 + lane];
        v[4 * i] = q.x; v[4 * i + 1] = q.y; v[4 * i + 2] = q.z; v[4 * i + 3] = q.w;
    }
    float m = v[0];
#pragma unroll
    for (int i = 1; i < 16; ++i) m = fmaxf(m, v[i]);
#pragma unroll
    for (int o = 16; o; o >>= 1) m = fmaxf(m, __shfl_xor_sync(0xffffffffu, m, o));
    float s = 0.f;
#pragma unroll
    for (int i = 0; i < 16; ++i) { v[i] = __expf(v[i] - m); s += v[i]; }
#pragma unroll
    for (int o = 16; o; o >>= 1) s += __shfl_xor_sync(0xffffffffu, s, o);
    const float inv = 1.f / s;
    __half2* P = (__half2*)(g_P16 + R * 512);
#pragma unroll
    for (int i = 0; i < 4; ++i) {
        int base = (i * 32 + lane) * 2;
        P[base]     = __floats2half2_rn(v[4 * i] * inv,     v[4 * i + 1] * inv);
        P[base + 1] = __floats2half2_rn(v[4 * i + 2] * inv, v[4 * i + 3] * inv);
    }
}

// out = P @ V (single fp16 product), CTA 128x320, 3-stage, smem-staged stores
__global__ __launch_bounds__(256) void out_kernel(float* __restrict__ out) {
    extern __shared__ char sm[];
    const u32 sb = s2u(sm);
    const int tid = threadIdx.x;
    const int lane = tid & 31, wid = tid >> 5;
    const int wm = wid >> 2, wn = wid & 3;
    const int t0 = blockIdx.x * 128;
    const int b = blockIdx.z & 15, h = blockIdx.z >> 4, hb = h * 16 + b;
    float acc[4][10][4]; ACC_ZERO(acc, 5);
    gemm1<8, 5>(sb,
                (const bf16*)(g_P16 + ((size_t)hb * 2048 + t0) * 512),
                (const bf16*)(g_V16 + (size_t)b * 320 * 512),
                512, acc);
    float* stg = (float*)sm;
#pragma unroll
    for (int mi = 0; mi < 4; ++mi)
#pragma unroll
        for (int ni = 0; ni < 10; ++ni) {
            int r = wm * 64 + mi * 16 + (lane >> 2);
            int c = wn * 80 + ni * 8 + 2 * (lane & 3);
            *(float2*)&stg[r * 328 + c]       = make_float2(acc[mi][ni][0], acc[mi][ni][1]);
            *(float2*)&stg[(r + 8) * 328 + c] = make_float2(acc[mi][ni][2], acc[mi][ni][3]);
        }
    __syncthreads();
    for (int i = tid; i < 128 * 75; i += 256) {
        int r = i / 75, c = (i - r * 75) * 4;
        *(float4*)&out[((size_t)hb * 2048 + t0 + r) * 300 + c] = *(float4*)&stg[r * 328 + c];
    }
}

extern "C" void kernel_launch(void* const* d_in, const int* in_sizes, int n_in,
                              void* d_out, int out_size) {
    (void)in_sizes; (void)n_in; (void)out_size;
    const float* in1 = (const float*)d_in[0];
    const float* in2 = (const float*)d_in[1];
    const float* W2  = (const float*)d_in[2];
    const float* b2  = (const float*)d_in[3];
    const float* W3  = (const float*)d_in[4];
    const float* b3  = (const float*)d_in[5];
    float* out = (float*)d_out;

    static bool inited = false;
    static cudaStream_t s1, s2;
    static cudaEvent_t eFork, e1, e2;
    if (!inited) {
        cudaStreamCreateWithFlags(&s1, cudaStreamNonBlocking);
        cudaStreamCreateWithFlags(&s2, cudaStreamNonBlocking);
        cudaEventCreateWithFlags(&eFork, cudaEventDisableTiming);
        cudaEventCreateWithFlags(&e1, cudaEventDisableTiming);
        cudaEventCreateWithFlags(&e2, cudaEventDisableTiming);
        cudaFuncSetAttribute(proj_mma, cudaFuncAttributeMaxDynamicSharedMemorySize, SMEM_PROJ);
        cudaFuncSetAttribute(scores_kernel, cudaFuncAttributeMaxDynamicSharedMemorySize, SMEM_GN4);
        cudaFuncSetAttribute(out_kernel, cudaFuncAttributeMaxDynamicSharedMemorySize, SMEM_OUT);
        inited = true;
    }

    // fork: branch1 = proj chain (s1), branch2 = vt (s2), main = split_in1
    cudaEventRecord(eFork, 0);
    cudaStreamWaitEvent(s1, eFork, 0);
    cudaStreamWaitEvent(s2, eFork, 0);

    split_in1<<<(int)((16L * 2048 * KP + 255) / 256), 256>>>(in1);

    split_in2<<<(int)((16L * 512 * KP + 255) / 256), 256, 0, s1>>>(in2);
    wsplit_kernel<<<(2 * 300 * 300 + 255) / 256, 256, 0, s1>>>(W2, W3);
    proj_mma<<<dim3(64, 6, 2), 256, SMEM_PROJ, s1>>>(b2, b3);
    cudaEventRecord(e1, s1);

    vt_kernel<<<dim3(16, 10, 16), dim3(32, 8), 0, s2>>>(in2);
    cudaEventRecord(e2, s2);

    // scores needs split_in1 + proj
    cudaStreamWaitEvent(0, e1, 0);
    scores_kernel<<<dim3(16, 2, 32), 256, SMEM_GN4>>>();
    softmax_kernel<<<8192, 256>>>();
    // out additionally needs vt
    cudaStreamWaitEvent(0, e2, 0);
    out_kernel<<<dim3(16, 1, 32), 256, SMEM_OUT>>>(out);
}